// round 10
// baseline (speedup 1.0000x reference)
#include <cuda_runtime.h>
#include <cuda_bf16.h>
#include <cstdint>

#define B_  2
#define LQ_ 2048
#define LK_ 2048

// ---------------- scratch (__device__ globals: no allocation) ----------------
__device__ float          g_QF[B_ * LQ_ * 64];        // [b][q][64]
__device__ float          g_KT[B_ * 64 * LK_];        // [b][j][k]
__device__ __nv_bfloat16  g_VT[B_ * LK_ * 256];       // [b][k][256]

// ---------------- packed f32x2 helpers ----------------
union F2 { unsigned long long u; float2 f; };

__device__ __forceinline__ void ffma2(F2& d, const F2& a, const F2& b) {
    asm("fma.rn.f32x2 %0, %1, %2, %0;" : "+l"(d.u) : "l"(a.u), "l"(b.u));
}
__device__ __forceinline__ void fmul2(F2& d, const F2& a) {
    asm("mul.rn.f32x2 %0, %0, %1;" : "+l"(d.u) : "l"(a.u));
}

// ---------------- tensor-core / async helpers ----------------
#define LDSM4T(r0, r1, r2, r3, addr) \
    asm volatile("ldmatrix.sync.aligned.m8n8.x4.trans.shared.b16 {%0,%1,%2,%3}, [%4];" \
        : "=r"(r0), "=r"(r1), "=r"(r2), "=r"(r3) : "r"(addr))
#define LDSM2T(r0, r1, addr) \
    asm volatile("ldmatrix.sync.aligned.m8n8.x2.trans.shared.b16 {%0,%1}, [%2];" \
        : "=r"(r0), "=r"(r1) : "r"(addr))
#define MMA16816(D, a0, a1, a2, a3, bb0, bb1) \
    asm volatile("mma.sync.aligned.m16n8k16.row.col.f32.bf16.bf16.f32 " \
        "{%0,%1,%2,%3}, {%4,%5,%6,%7}, {%8,%9}, {%0,%1,%2,%3};" \
        : "+f"(D[0]), "+f"(D[1]), "+f"(D[2]), "+f"(D[3]) \
        : "r"(a0), "r"(a1), "r"(a2), "r"(a3), "r"(bb0), "r"(bb1))
#define CVT_BF2(dst, hi, lo) \
    asm("cvt.rn.bf16x2.f32 %0, %1, %2;" : "=r"(dst) : "f"(hi), "f"(lo))
#define CP16(dst, src) \
    asm volatile("cp.async.cg.shared.global [%0], [%1], 16;" :: "r"(dst), "l"(src))
#define CP_COMMIT() asm volatile("cp.async.commit_group;")
#define CP_WAIT0()  asm volatile("cp.async.wait_group 0;")

// =====================================================================
// Q/K projection. grid (128, B, 2): blockIdx.z 0 -> Q, 1 -> K.
// 16 rows/block; warp-uniform stream split (tid&63: 0-31 it, 32-63 ctx);
// 4 rows/thread = 4 independent FFMA chains.
// =====================================================================
__global__ __launch_bounds__(256) void proj_qk(
    const float* __restrict__ qit, const float* __restrict__ qctx,
    const float* __restrict__ kit, const float* __restrict__ kctx,
    const float* __restrict__ Wq_it, const float* __restrict__ Wq_ctx,
    const float* __restrict__ Wk_it, const float* __restrict__ Wk_ctx)
{
    __shared__ float sWit[256 * 32];   // 32KB
    __shared__ float sWct[128 * 32];   // 16KB
    const int mode = blockIdx.z;
    const float* in_it = mode ? kit : qit;
    const float* in_ct = mode ? kctx : qctx;
    const float* W_it  = mode ? Wk_it : Wq_it;
    const float* W_ct  = mode ? Wk_ctx : Wq_ctx;
    const int b = blockIdx.y;
    const int col = threadIdx.x & 63;
    const int isCtx = col >> 5;                     // warp-uniform
    const int j = col & 31;
    const int row0 = blockIdx.x * 16 + (threadIdx.x >> 6) * 4;

    for (int idx = threadIdx.x; idx < 256 * 32; idx += 256) sWit[idx] = W_it[idx];
    for (int idx = threadIdx.x; idx < 128 * 32; idx += 256) sWct[idx] = W_ct[idx];
    __syncthreads();

    const float* in = isCtx ? in_ct : in_it;
    const float* sW = isCtx ? sWct : sWit;
    const int nin4 = isCtx ? 32 : 64;               // float4 per input row

    const float4* p = (const float4*)(in + ((size_t)b * 2048 + row0) * (nin4 * 4));
    float a[4] = {0.f, 0.f, 0.f, 0.f};

    #pragma unroll 4
    for (int i4 = 0; i4 < nin4; i4++) {
        float4 v[4];
        #pragma unroll
        for (int r = 0; r < 4; r++) v[r] = p[r * nin4 + i4];
        #pragma unroll
        for (int ii = 0; ii < 4; ii++) {
            const float w = sW[(i4 * 4 + ii) * 32 + j];
            #pragma unroll
            for (int r = 0; r < 4; r++)
                a[r] = fmaf(((const float*)&v[r])[ii], w, a[r]);
        }
    }

    if (mode == 0) {
        #pragma unroll
        for (int r = 0; r < 4; r++)
            g_QF[((size_t)b * 2048 + row0 + r) * 64 + col] = a[r];
    } else {
        #pragma unroll
        for (int r = 0; r < 4; r++)
            g_KT[((size_t)b * 64 + col) * 2048 + row0 + r] = a[r];
    }
}

// =====================================================================
// V projection: VT[b][k][hd] = keys_it @ Wv (bf16 out). grid (128, B), 256 thr.
// =====================================================================
__global__ __launch_bounds__(256) void proj_v(
    const float* __restrict__ keys_it, const float* __restrict__ Wv)
{
    __shared__ float sKT[256][18];
    const int b = blockIdx.y;
    const int kbase = blockIdx.x * 16;

    for (int idx = threadIdx.x; idx < 16 * 256; idx += 256) {
        const int r = idx >> 8, i = idx & 255;
        sKT[i][r] = keys_it[((size_t)b * 2048 + kbase + r) * 256 + i];
    }
    __syncthreads();

    const int hd = threadIdx.x;
    F2 acc[8];
    #pragma unroll
    for (int p = 0; p < 8; p++) acc[p].f = make_float2(0.0f, 0.0f);

    #pragma unroll 8
    for (int i = 0; i < 256; i++) {
        const float w = Wv[i * 256 + hd];
        F2 w2; w2.f = make_float2(w, w);
        #pragma unroll
        for (int p = 0; p < 8; p++) {
            F2 kp; kp.f = *reinterpret_cast<const float2*>(&sKT[i][2 * p]);
            ffma2(acc[p], kp, w2);
        }
    }

    __nv_bfloat16* o = g_VT + ((size_t)b * 2048 + kbase) * 256 + hd;
    #pragma unroll
    for (int p = 0; p < 8; p++) {
        o[(size_t)(2 * p) * 256]     = __float2bfloat16(acc[p].f.x);
        o[(size_t)(2 * p + 1) * 256] = __float2bfloat16(acc[p].f.y);
    }
}

// =====================================================================
// Attention: grid (LQ/16, B), 256 threads (warp = head), cp.async pipelined.
// smem layout (bytes):
//   sQT f32[64][16]        @ 0       (4096)
//   sK  f32[64][64]        @ 4096    (16384)   cp.async, single buffer
//   sV0 bf16[64][264]      @ 20480   (33792)   cp.async double buffer;
//   sV1 bf16[64][264]      @ 54272   (33792)   cols 256..263 = ones-block
//   sE  bf16[8][64][24]    @ 88064   (24576)
//   sZ  f32[8][16]         @ 112640  (512)
// =====================================================================
#define ATTN_SMEM 113152

__global__ __launch_bounds__(256, 2) void attn_kernel(
    const float* __restrict__ noise, const float* __restrict__ sigma,
    const float* __restrict__ W_hdp, const float* __restrict__ b_hdp,
    const int* __restrict__ key_mask, const int* __restrict__ query_mask,
    const float* __restrict__ queries_it, float* __restrict__ out)
{
    extern __shared__ char dyn[];
    float*         sQT = (float*)dyn;
    float*         sK  = (float*)(dyn + 4096);
    __nv_bfloat16* sV0 = (__nv_bfloat16*)(dyn + 20480);
    __nv_bfloat16* sV1 = (__nv_bfloat16*)(dyn + 54272);
    char*          sEc = dyn + 88064;
    float*         sZ  = (float*)(dyn + 112640);

    const int tid  = threadIdx.x;
    const int lane = tid & 31;
    const int b = blockIdx.y;
    const int qbase = blockIdx.x * 16;
    const float SCALE = 0.17677669529663687f;   // 1/sqrt(32)

    const uint32_t sm_u  = (uint32_t)__cvta_generic_to_shared(dyn);
    const uint32_t sK_u  = sm_u + 4096;
    const uint32_t sV0_u = sm_u + 20480;
    const uint32_t sV1_u = sm_u + 54272;
    const uint32_t sE_u  = sm_u + 88064;

    // per-thread staging geometry
    const int kj  = tid >> 4,  kseg = tid & 15;   // K: (j-row block, 16B seg)
    const int vkr = tid >> 5,  vseg = tid & 31;   // V: (k-row block, 16B seg)

    const float* KTb = g_KT + (size_t)b * 64 * LK_;
    const __nv_bfloat16* Vb = g_VT + (size_t)b * LK_ * 256;
    const float* n0base = noise + (size_t)(b * 2 + 0) * LQ_ * LK_;
    const float* n1base = noise + (size_t)(b * 2 + 1) * LQ_ * LK_;

    // phase A ids
    const int ka  = tid & 63;
    const int qa4 = (tid >> 6) << 2;
    // phase B ids: warp = head
    const int h = tid >> 5;

    // ---- prologue: stage tile 0 (V then K), load noise(0) ----
    #pragma unroll
    for (int p = 0; p < 8; p++) {
        const int idx = tid + 256 * p;
        const int kr = idx >> 5, seg = idx & 31;
        CP16(sV0_u + kr * 528 + seg * 16, Vb + (size_t)kr * 256 + seg * 8);
    }
    #pragma unroll
    for (int p = 0; p < 4; p++) {
        const int idx4 = tid + 256 * p;
        const int jj = idx4 >> 4, seg = idx4 & 15;
        CP16(sK_u + jj * 256 + seg * 16, KTb + (size_t)jj * LK_ + seg * 4);
    }
    CP_COMMIT();

    float n0v[4], n1v[4];
    #pragma unroll
    for (int qi = 0; qi < 4; qi++) {
        n0v[qi] = n0base[(size_t)(qbase + qa4 + qi) * LK_ + ka];
        n1v[qi] = n1base[(size_t)(qbase + qa4 + qi) * LK_ + ka];
    }
    float kmf = key_mask[b * LK_ + ka] ? 1.0f : 0.0f;

    // Q tile transposed into shared: sQT[j][q]
    for (int idx = tid; idx < 1024; idx += 256) {
        const int jj = idx & 63, q = idx >> 6;
        sQT[jj * 16 + q] = g_QF[((size_t)b * LQ_ + qbase + q) * 64 + jj];
    }
    // ones-block in both V buffers (cols 256..263)
    for (int idx = tid; idx < 512; idx += 256) {
        const int r = idx >> 3, c = idx & 7;
        const __nv_bfloat16 v = __float2bfloat16(c == 0 ? 1.0f : 0.0f);
        sV0[r * 264 + 256 + c] = v;
        sV1[r * 264 + 256 + c] = v;
    }

    const float s0 = sigma[b * 2 + 0], s1 = sigma[b * 2 + 1];
    const float sig0sq = s0 * s0, sig1sq = s1 * s1;
    F2 w02[4], w12[4], bb2[4];
    #pragma unroll
    for (int p = 0; p < 4; p++) {
        w02[p].f = make_float2(W_hdp[2 * p] * SCALE,     W_hdp[2 * p + 1] * SCALE);
        w12[p].f = make_float2(W_hdp[8 + 2 * p] * SCALE, W_hdp[8 + 2 * p + 1] * SCALE);
        bb2[p].f = make_float2(b_hdp[2 * p] * SCALE,     b_hdp[2 * p + 1] * SCALE);
    }
    F2 P4; P4.f = make_float2(1.0f / 24.0f, 1.0f / 24.0f);
    F2 P3; P3.f = make_float2(1.0f / 6.0f,  1.0f / 6.0f);
    F2 P2; P2.f = make_float2(0.5f, 0.5f);
    F2 ONE; ONE.f = make_float2(1.0f, 1.0f);

    // ldmatrix per-lane addresses
    const int a_row  = (lane & 7) + ((lane >> 4) << 3);
    const int a_colb = ((lane >> 3) & 1) * 16;
    const uint32_t aBase = sE_u + h * 3072 + a_row * 48 + a_colb;
    const int b_row  = (lane & 7) + (((lane >> 3) & 1) << 3);
    const int b_colb = (lane >> 4) * 16;
    const uint32_t bBase0 = sV0_u + b_row * 528 + h * 64 + b_colb;
    const uint32_t oBase0 = sV0_u + b_row * 528 + 512;

    float d[5][4];
    #pragma unroll
    for (int t = 0; t < 5; t++)
        #pragma unroll
        for (int c = 0; c < 4; c++) d[t][c] = 0.0f;

    CP_WAIT0();
    __syncthreads();

    for (int kt = 0; kt < LK_ / 64; kt++) {
        const int cur = kt & 1;
        const int tn = (kt + 1 < LK_ / 64) ? (kt + 1) : (LK_ / 64 - 1);
        const int kbaseN = tn * 64;

        // ---- prefetch V(tn) into the other buffer (full-tile window) ----
        const uint32_t vdst = (cur ? sV0_u : sV1_u) + vkr * 528 + vseg * 16;
        #pragma unroll
        for (int p = 0; p < 8; p++)
            CP16(vdst + p * 8 * 528, Vb + (size_t)(kbaseN + vkr + 8 * p) * 256 + vseg * 8);
        CP_COMMIT();

        // ---- prefetch noise(tn) + key_mask(tn) into regs ----
        float nn0[4], nn1[4];
        #pragma unroll
        for (int qi = 0; qi < 4; qi++) {
            nn0[qi] = n0base[(size_t)(qbase + qa4 + qi) * LK_ + kbaseN + ka];
            nn1[qi] = n1base[(size_t)(qbase + qa4 + qi) * LK_ + kbaseN + ka];
        }
        const float nkm = key_mask[b * LK_ + kbaseN + ka] ? 1.0f : 0.0f;

        // ---- Phase A: dual-stream dots from sK ----
        F2 sit01, sit23, sct01, sct23;
        sit01.f = make_float2(0.0f, 0.0f); sit23.f = make_float2(0.0f, 0.0f);
        sct01.f = make_float2(0.0f, 0.0f); sct23.f = make_float2(0.0f, 0.0f);

        #pragma unroll 8
        for (int jj = 0; jj < 32; jj++) {
            const float kv = sK[jj * 64 + ka];
            F2 kv2; kv2.f = make_float2(kv, kv);
            const float4 q4 = *(const float4*)(sQT + jj * 16 + qa4);
            F2 a; a.f = make_float2(q4.x, q4.y);
            F2 c; c.f = make_float2(q4.z, q4.w);
            ffma2(sit01, a, kv2);
            ffma2(sit23, c, kv2);
        }
        #pragma unroll 8
        for (int jj = 32; jj < 64; jj++) {
            const float kv = sK[jj * 64 + ka];
            F2 kv2; kv2.f = make_float2(kv, kv);
            const float4 q4 = *(const float4*)(sQT + jj * 16 + qa4);
            F2 a; a.f = make_float2(q4.x, q4.y);
            F2 c; c.f = make_float2(q4.z, q4.w);
            ffma2(sct01, a, kv2);
            ffma2(sct23, c, kv2);
        }

        const float sit[4] = {sit01.f.x, sit01.f.y, sit23.f.x, sit23.f.y};
        const float sct[4] = {sct01.f.x, sct01.f.y, sct23.f.x, sct23.f.y};
        F2 km2; km2.f = make_float2(kmf, kmf);

        F2 A2[4], C2v[4];
        #pragma unroll
        for (int qi = 0; qi < 4; qi++) {
            const float Av = fmaf(sig0sq, n0v[qi], sit[qi]);
            const float Cv = fmaf(sig1sq, n1v[qi], sct[qi]);
            A2[qi].f = make_float2(Av, Av);
            C2v[qi].f = make_float2(Cv, Cv);
        }

        // ---- per head-pair: poly exp -> bf16 store sE[h][k][q] ----
        #pragma unroll
        for (int p = 0; p < 4; p++) {
            float e0[4], e1[4];
            #pragma unroll
            for (int qi = 0; qi < 4; qi++) {
                F2 x = bb2[p];
                ffma2(x, A2[qi], w02[p]);
                ffma2(x, C2v[qi], w12[p]);
                F2 t = P3;  ffma2(t, x, P4);
                F2 t2 = P2; ffma2(t2, x, t);
                F2 t3 = ONE; ffma2(t3, x, t2);
                F2 t4 = ONE; ffma2(t4, x, t3);
                fmul2(t4, km2);
                e0[qi] = t4.f.x;
                e1[qi] = t4.f.y;
            }
            uint32_t r0, r1, r2, r3;
            CVT_BF2(r0, e0[1], e0[0]);
            CVT_BF2(r1, e0[3], e0[2]);
            CVT_BF2(r2, e1[1], e1[0]);
            CVT_BF2(r3, e1[3], e1[2]);
            *(uint2*)(sEc + (2 * p)     * 3072 + ka * 48 + qa4 * 2) = make_uint2(r0, r1);
            *(uint2*)(sEc + (2 * p + 1) * 3072 + ka * 48 + qa4 * 2) = make_uint2(r2, r3);
        }
        __syncthreads();   // sE ready; sK fully consumed

        // ---- prefetch K(tn) into sK (phase-B window) ----
        #pragma unroll
        for (int p = 0; p < 4; p++) {
            const int idx4 = tid + 256 * p;
            const int jj = idx4 >> 4, seg = idx4 & 15;
            CP16(sK_u + jj * 256 + seg * 16,
                 KTb + (size_t)jj * LK_ + kbaseN + seg * 4);
        }
        CP_COMMIT();

        // ---- Phase B: tensor-core PV (+Z via ones column) ----
        const uint32_t bB = bBase0 + cur * 33792;
        const uint32_t oB = oBase0 + cur * 33792;
        #pragma unroll
        for (int s = 0; s < 4; s++) {
            uint32_t a0, a1, a2, a3;
            LDSM4T(a0, a1, a2, a3, aBase + s * 768);
            #pragma unroll
            for (int t = 0; t < 2; t++) {
                uint32_t v0, v1, v2, v3;
                LDSM4T(v0, v1, v2, v3, bB + s * 8448 + t * 32);
                MMA16816(d[2 * t],     a0, a1, a2, a3, v0, v1);
                MMA16816(d[2 * t + 1], a0, a1, a2, a3, v2, v3);
            }
            uint32_t o0, o1;
            LDSM2T(o0, o1, oB + s * 8448);
            MMA16816(d[4], a0, a1, a2, a3, o0, o1);
        }

        CP_WAIT0();        // K(tn), V(tn) arrived
        __syncthreads();   // safe to read sK / other V buffer next iter

        // rotate prefetched noise/mask
        #pragma unroll
        for (int qi = 0; qi < 4; qi++) { n0v[qi] = nn0[qi]; n1v[qi] = nn1[qi]; }
        kmf = nkm;
    }

    // ---- Z: ones column (frag col 0 of n-tile 4), lanes with lane%4==0 ----
    if ((lane & 3) == 0) {
        sZ[h * 16 + (lane >> 2)]     = d[4][0];
        sZ[h * 16 + (lane >> 2) + 8] = d[4][2];
    }
    __syncthreads();

    // ---- epilogue: out = queries_it + (acc/Z) * query_mask ----
    #pragma unroll
    for (int rr = 0; rr < 2; rr++) {
        const int q = (lane >> 2) + rr * 8;
        const int qm = query_mask[b * LQ_ + qbase + q];
        const float invz = qm ? __frcp_rn(sZ[h * 16 + q]) : 0.0f;
        const size_t rowbase = ((size_t)b * LQ_ + qbase + q) * 256 + h * 32 + (lane & 3) * 2;
        #pragma unroll
        for (int t = 0; t < 4; t++) {
            float2 r = *(const float2*)(queries_it + rowbase + t * 8);
            r.x = fmaf(d[t][rr * 2 + 0], invz, r.x);
            r.y = fmaf(d[t][rr * 2 + 1], invz, r.y);
            *(float2*)(out + rowbase + t * 8) = r;
        }
    }
}

// =====================================================================
extern "C" void kernel_launch(void* const* d_in, const int* in_sizes, int n_in,
                              void* d_out, int out_size)
{
    (void)in_sizes; (void)n_in; (void)out_size;
    const float* queries_it  = (const float*)d_in[0];
    const float* queries_ctx = (const float*)d_in[1];
    const float* keys_it     = (const float*)d_in[2];
    const float* keys_ctx    = (const float*)d_in[3];
    const float* sigma       = (const float*)d_in[4];
    const float* noise       = (const float*)d_in[5];
    const float* Wq_it       = (const float*)d_in[6];
    const float* Wk_it       = (const float*)d_in[7];
    const float* Wq_ctx      = (const float*)d_in[8];
    const float* Wk_ctx      = (const float*)d_in[9];
    const float* Wv          = (const float*)d_in[10];
    const float* W_hdp       = (const float*)d_in[11];
    const float* b_hdp       = (const float*)d_in[12];
    const int*   key_mask    = (const int*)d_in[13];
    const int*   query_mask  = (const int*)d_in[14];
    float* out = (float*)d_out;

    cudaFuncSetAttribute(attn_kernel, cudaFuncAttributeMaxDynamicSharedMemorySize, ATTN_SMEM);

    proj_qk<<<dim3(128, B_, 2), 256>>>(queries_it, queries_ctx, keys_it, keys_ctx,
                                       Wq_it, Wq_ctx, Wk_it, Wk_ctx);
    proj_v<<<dim3(128, B_), 256>>>(keys_it, Wv);
    attn_kernel<<<dim3(LQ_ / 16, B_), 256, ATTN_SMEM>>>(
        noise, sigma, W_hdp, b_hdp, key_mask, query_mask, queries_it, out);
}

// round 11
// speedup vs baseline: 2.0619x; 2.0619x over previous
#include <cuda_runtime.h>
#include <cuda_bf16.h>
#include <cstdint>

#define B_  2
#define LQ_ 2048
#define LK_ 2048

// ---------------- scratch (__device__ globals: no allocation) ----------------
__device__ __nv_bfloat16  g_QFh[B_ * LQ_ * 64];       // [b][q][64]  bf16 (it | ctx)
__device__ __nv_bfloat16  g_KTh[B_ * 64 * LK_];       // [b][j][k]   bf16 (rows j: 0-31 it, 32-63 ctx)
__device__ __nv_bfloat16  g_VT [B_ * LK_ * 256];      // [b][k][256] bf16

// ---------------- packed f32x2 helpers ----------------
union F2 { unsigned long long u; float2 f; };

__device__ __forceinline__ void ffma2(F2& d, const F2& a, const F2& b) {
    asm("fma.rn.f32x2 %0, %1, %2, %0;" : "+l"(d.u) : "l"(a.u), "l"(b.u));
}
__device__ __forceinline__ void fmul2(F2& d, const F2& a) {
    asm("mul.rn.f32x2 %0, %0, %1;" : "+l"(d.u) : "l"(a.u));
}

// ---------------- tensor-core helpers ----------------
#define LDSM4(r0, r1, r2, r3, addr) \
    asm volatile("ldmatrix.sync.aligned.m8n8.x4.shared.b16 {%0,%1,%2,%3}, [%4];" \
        : "=r"(r0), "=r"(r1), "=r"(r2), "=r"(r3) : "r"(addr))
#define LDSM4T(r0, r1, r2, r3, addr) \
    asm volatile("ldmatrix.sync.aligned.m8n8.x4.trans.shared.b16 {%0,%1,%2,%3}, [%4];" \
        : "=r"(r0), "=r"(r1), "=r"(r2), "=r"(r3) : "r"(addr))
#define LDSM2T(r0, r1, addr) \
    asm volatile("ldmatrix.sync.aligned.m8n8.x2.trans.shared.b16 {%0,%1}, [%2];" \
        : "=r"(r0), "=r"(r1) : "r"(addr))
#define MMA16816(D, a0, a1, a2, a3, bb0, bb1) \
    asm volatile("mma.sync.aligned.m16n8k16.row.col.f32.bf16.bf16.f32 " \
        "{%0,%1,%2,%3}, {%4,%5,%6,%7}, {%8,%9}, {%0,%1,%2,%3};" \
        : "+f"(D[0]), "+f"(D[1]), "+f"(D[2]), "+f"(D[3]) \
        : "r"(a0), "r"(a1), "r"(a2), "r"(a3), "r"(bb0), "r"(bb1))
#define CVT_BF2(dst, hi, lo) \
    asm("cvt.rn.bf16x2.f32 %0, %1, %2;" : "=r"(dst) : "f"(hi), "f"(lo))

// =====================================================================
// Q/K projection (R8-proven form, bf16 outputs).
// grid (64, B, 2): z=0 -> Q, z=1 -> K. 32 rows/block, 4 rows/thread.
// =====================================================================
__global__ __launch_bounds__(256) void proj_qk(
    const float* __restrict__ qit, const float* __restrict__ qctx,
    const float* __restrict__ kit, const float* __restrict__ kctx,
    const float* __restrict__ Wq_it, const float* __restrict__ Wq_ctx,
    const float* __restrict__ Wk_it, const float* __restrict__ Wk_ctx)
{
    __shared__ float sWit[256 * 32];   // 32KB
    __shared__ float sWct[128 * 32];   // 16KB
    const int mode = blockIdx.z;
    const float* in_it = mode ? kit : qit;
    const float* in_ct = mode ? kctx : qctx;
    const float* W_it  = mode ? Wk_it : Wq_it;
    const float* W_ct  = mode ? Wk_ctx : Wq_ctx;
    const int b = blockIdx.y;
    const int j  = threadIdx.x & 31;
    const int rl = threadIdx.x >> 5;
    const int row0 = blockIdx.x * 32 + rl * 4;

    for (int idx = threadIdx.x; idx < 256 * 32; idx += 256) sWit[idx] = W_it[idx];
    for (int idx = threadIdx.x; idx < 128 * 32; idx += 256) sWct[idx] = W_ct[idx];
    __syncthreads();

    const float4* pit = (const float4*)(in_it + ((size_t)b * 2048 + row0) * 256);
    const float4* pct = (const float4*)(in_ct + ((size_t)b * 2048 + row0) * 128);

    float ai[4] = {0.f, 0.f, 0.f, 0.f};
    float ac[4] = {0.f, 0.f, 0.f, 0.f};

    #pragma unroll 4
    for (int i4 = 0; i4 < 64; i4++) {
        float4 v[4];
        #pragma unroll
        for (int r = 0; r < 4; r++) v[r] = pit[r * 64 + i4];
        #pragma unroll
        for (int ii = 0; ii < 4; ii++) {
            const float w = sWit[(i4 * 4 + ii) * 32 + j];
            #pragma unroll
            for (int r = 0; r < 4; r++)
                ai[r] = fmaf(((const float*)&v[r])[ii], w, ai[r]);
        }
    }
    #pragma unroll 4
    for (int i4 = 0; i4 < 32; i4++) {
        float4 v[4];
        #pragma unroll
        for (int r = 0; r < 4; r++) v[r] = pct[r * 32 + i4];
        #pragma unroll
        for (int ii = 0; ii < 4; ii++) {
            const float w = sWct[(i4 * 4 + ii) * 32 + j];
            #pragma unroll
            for (int r = 0; r < 4; r++)
                ac[r] = fmaf(((const float*)&v[r])[ii], w, ac[r]);
        }
    }

    if (mode == 0) {
        #pragma unroll
        for (int r = 0; r < 4; r++) {
            __nv_bfloat16* o = g_QFh + ((size_t)b * 2048 + row0 + r) * 64;
            o[j]      = __float2bfloat16(ai[r]);
            o[32 + j] = __float2bfloat16(ac[r]);
        }
    } else {
        // pack 4 consecutive-k bf16 per 8B store: g_KTh[j][row0..row0+3]
        __nv_bfloat16 pi[4], pc[4];
        #pragma unroll
        for (int r = 0; r < 4; r++) { pi[r] = __float2bfloat16(ai[r]); pc[r] = __float2bfloat16(ac[r]); }
        *(uint2*)(g_KTh + ((size_t)b * 64 + j)      * 2048 + row0) = *(const uint2*)pi;
        *(uint2*)(g_KTh + ((size_t)b * 64 + 32 + j) * 2048 + row0) = *(const uint2*)pc;
    }
}

// =====================================================================
// V projection: VT[b][k][hd] = keys_it @ Wv (bf16). grid (128, B), 256 thr.
// =====================================================================
__global__ __launch_bounds__(256) void proj_v(
    const float* __restrict__ keys_it, const float* __restrict__ Wv)
{
    __shared__ float sKT[256][18];
    const int b = blockIdx.y;
    const int kbase = blockIdx.x * 16;

    for (int idx = threadIdx.x; idx < 16 * 256; idx += 256) {
        const int r = idx >> 8, i = idx & 255;
        sKT[i][r] = keys_it[((size_t)b * 2048 + kbase + r) * 256 + i];
    }
    __syncthreads();

    const int hd = threadIdx.x;
    F2 acc[8];
    #pragma unroll
    for (int p = 0; p < 8; p++) acc[p].f = make_float2(0.0f, 0.0f);

    #pragma unroll 8
    for (int i = 0; i < 256; i++) {
        const float w = Wv[i * 256 + hd];
        F2 w2; w2.f = make_float2(w, w);
        #pragma unroll
        for (int p = 0; p < 8; p++) {
            F2 kp; kp.f = *reinterpret_cast<const float2*>(&sKT[i][2 * p]);
            ffma2(acc[p], kp, w2);
        }
    }

    __nv_bfloat16* o = g_VT + ((size_t)b * 2048 + kbase) * 256 + hd;
    #pragma unroll
    for (int p = 0; p < 8; p++) {
        o[(size_t)(2 * p) * 256]     = __float2bfloat16(acc[p].f.x);
        o[(size_t)(2 * p + 1) * 256] = __float2bfloat16(acc[p].f.y);
    }
}

// =====================================================================
// Attention: grid (LQ/16, B), 256 threads.
// Phase A: per-warp (= key-octet) tensor-core QK for both streams,
//          fragment-local noise + per-head poly-exp -> sE2[h][q][k] bf16.
// Phase B: per-warp (= head) tensor-core PV with ones-column Z.
// smem (bytes): sQh bf16[16][72] @0 (2304) | sKh bf16[64][72] @2304 (9216)
//   | sV bf16[64][264] @11520 (33792, cols 256..263 ones)
//   | sE2 bf16[8][16][72] @45312 (18432) | sZ f32[8][16] @63744 (512)
// total 64256 -> 2 blocks/SM.
// =====================================================================
#define ATTN_SMEM 64256

__global__ __launch_bounds__(256, 2) void attn_kernel(
    const float* __restrict__ noise, const float* __restrict__ sigma,
    const float* __restrict__ W_hdp, const float* __restrict__ b_hdp,
    const int* __restrict__ key_mask, const int* __restrict__ query_mask,
    const float* __restrict__ queries_it, float* __restrict__ out)
{
    extern __shared__ char dyn[];
    __nv_bfloat16* sV  = (__nv_bfloat16*)(dyn + 11520);
    char*          sE2 = dyn + 45312;
    float*         sZ  = (float*)(dyn + 63744);

    const int tid  = threadIdx.x;
    const int lane = tid & 31;
    const int wid  = tid >> 5;
    const int b = blockIdx.y;
    const int qbase = blockIdx.x * 16;
    const float SCALE = 0.17677669529663687f;   // 1/sqrt(32)

    const uint32_t sm_u   = (uint32_t)__cvta_generic_to_shared(dyn);
    const uint32_t sQh_u  = sm_u;
    const uint32_t sKh_u  = sm_u + 2304;
    const uint32_t sV_u   = sm_u + 11520;
    const uint32_t sE2_u  = sm_u + 45312;

    const __nv_bfloat16* QFb = g_QFh + (size_t)b * LQ_ * 64;
    const __nv_bfloat16* KTb = g_KTh + (size_t)b * 64 * LK_;
    const __nv_bfloat16* Vb  = g_VT  + (size_t)b * LK_ * 256;
    const float* n0base = noise + (size_t)(b * 2 + 0) * LQ_ * LK_;
    const float* n1base = noise + (size_t)(b * 2 + 1) * LQ_ * LK_;

    // ---- prologue: stage Q tile (16 rows x 128B) ----
    if (tid < 128) {
        const int r = tid >> 3, seg = tid & 7;
        *(uint4*)(dyn + r * 144 + seg * 16) =
            *(const uint4*)(QFb + (size_t)(qbase + r) * 64 + seg * 8);
    }
    // ones-block in sV cols 256..263 (static)
    for (int idx = tid; idx < 512; idx += 256) {
        const int r = idx >> 3, c = idx & 7;
        sV[r * 264 + 256 + c] = __float2bfloat16(c == 0 ? 1.0f : 0.0f);
    }
    __syncthreads();

    // ---- Q A-fragments (persistent): qa[c] = j-chunk c (c0,1 = it; c2,3 = ctx) ----
    uint32_t qa[4][4];
    {
        const uint32_t qaddr = sQh_u
            + ((lane & 7) + ((lane >> 3) & 1) * 8) * 144
            + (lane >> 4) * 16;
        #pragma unroll
        for (int c = 0; c < 4; c++)
            LDSM4(qa[c][0], qa[c][1], qa[c][2], qa[c][3], qaddr + c * 32);
    }

    const float s0 = sigma[b * 2 + 0], s1 = sigma[b * 2 + 1];
    const float sig0sq = s0 * s0, sig1sq = s1 * s1;
    F2 w02[4], w12[4], bb2[4];
    #pragma unroll
    for (int p = 0; p < 4; p++) {
        w02[p].f = make_float2(W_hdp[2 * p] * SCALE,     W_hdp[2 * p + 1] * SCALE);
        w12[p].f = make_float2(W_hdp[8 + 2 * p] * SCALE, W_hdp[8 + 2 * p + 1] * SCALE);
        bb2[p].f = make_float2(b_hdp[2 * p] * SCALE,     b_hdp[2 * p + 1] * SCALE);
    }
    F2 P4; P4.f = make_float2(1.0f / 24.0f, 1.0f / 24.0f);
    F2 P3; P3.f = make_float2(1.0f / 6.0f,  1.0f / 6.0f);
    F2 P2; P2.f = make_float2(0.5f, 0.5f);
    F2 ONE; ONE.f = make_float2(1.0f, 1.0f);

    // phase A lane geometry (warp = key-octet wid)
    const int q_lo = lane >> 2;
    const int k0   = 8 * wid + 2 * (lane & 3);
    const uint32_t kFragAddr = sKh_u
        + (((lane & 15) & 7) + (((lane & 15) >> 3) & 1) * 8) * 144
        + wid * 16;

    // phase B lane geometry (warp = head wid)
    const uint32_t aBase = sE2_u + wid * 2304
        + ((lane & 7) + ((lane >> 3) & 1) * 8) * 144
        + (lane >> 4) * 16;
    const int b_row  = (lane & 7) + (((lane >> 3) & 1) << 3);
    const int b_colb = (lane >> 4) * 16;
    const uint32_t bBase = sV_u + b_row * 528 + wid * 64 + b_colb;
    const uint32_t oBase = sV_u + b_row * 528 + 512;

    float d[5][4];
    #pragma unroll
    for (int t = 0; t < 5; t++)
        #pragma unroll
        for (int c = 0; c < 4; c++) d[t][c] = 0.0f;

    for (int kt = 0; kt < LK_ / 64; kt++) {
        const int kbase = kt * 64;
        const int kg = kbase + k0;

        // ---- noise + mask (fragment-matched) ----
        const float2 n0a = *(const float2*)(n0base + (size_t)(qbase + q_lo)     * LK_ + kg);
        const float2 n0b = *(const float2*)(n0base + (size_t)(qbase + q_lo + 8) * LK_ + kg);
        const float2 n1a = *(const float2*)(n1base + (size_t)(qbase + q_lo)     * LK_ + kg);
        const float2 n1b = *(const float2*)(n1base + (size_t)(qbase + q_lo + 8) * LK_ + kg);
        const int2 kmv = *(const int2*)(key_mask + b * LK_ + kg);
        const float km0 = kmv.x ? 1.0f : 0.0f;
        const float km1 = kmv.y ? 1.0f : 0.0f;

        // ---- stage K (8KB) + V (32KB) tiles ----
        {
            const int r = tid >> 3, seg = tid & 7;          // K: 2 chunks/thread
            *(uint4*)(dyn + 2304 + r * 144 + seg * 16) =
                *(const uint4*)(KTb + (size_t)r * LK_ + kbase + seg * 8);
            const int r2 = r + 32;
            *(uint4*)(dyn + 2304 + r2 * 144 + seg * 16) =
                *(const uint4*)(KTb + (size_t)r2 * LK_ + kbase + seg * 8);
        }
        #pragma unroll
        for (int p = 0; p < 8; p++) {
            const int idx = tid + 256 * p;
            const int kr = idx >> 5, seg = idx & 31;
            *(uint4*)((char*)sV + kr * 528 + seg * 16) =
                *(const uint4*)(Vb + (size_t)(kbase + kr) * 256 + seg * 8);
        }
        __syncthreads();

        // ---- Phase A: QK via tensor cores (both streams) ----
        float dit[4] = {0.f, 0.f, 0.f, 0.f};
        float dct[4] = {0.f, 0.f, 0.f, 0.f};
        {
            uint32_t b0, b1;
            LDSM2T(b0, b1, kFragAddr);                 // it, j 0-15
            MMA16816(dit, qa[0][0], qa[0][1], qa[0][2], qa[0][3], b0, b1);
            LDSM2T(b0, b1, kFragAddr + 16 * 144);      // it, j 16-31
            MMA16816(dit, qa[1][0], qa[1][1], qa[1][2], qa[1][3], b0, b1);
            LDSM2T(b0, b1, kFragAddr + 32 * 144);      // ctx, j 32-47
            MMA16816(dct, qa[2][0], qa[2][1], qa[2][2], qa[2][3], b0, b1);
            LDSM2T(b0, b1, kFragAddr + 48 * 144);      // ctx, j 48-63
            MMA16816(dct, qa[3][0], qa[3][1], qa[3][2], qa[3][3], b0, b1);
        }

        // ---- noise add + per-head poly exp -> sE2[h][q][k] (bf16 pairs) ----
        #pragma unroll
        for (int half = 0; half < 2; half++) {
            const int i0 = half * 2;                   // c0/c1 or c2/c3
            const int q  = q_lo + half * 8;
            const float A0 = fmaf(sig0sq, half ? n0b.x : n0a.x, dit[i0]);
            const float A1 = fmaf(sig0sq, half ? n0b.y : n0a.y, dit[i0 + 1]);
            const float C0 = fmaf(sig1sq, half ? n1b.x : n1a.x, dct[i0]);
            const float C1 = fmaf(sig1sq, half ? n1b.y : n1a.y, dct[i0 + 1]);
            F2 A0v; A0v.f = make_float2(A0, A0);
            F2 A1v; A1v.f = make_float2(A1, A1);
            F2 C0v; C0v.f = make_float2(C0, C0);
            F2 C1v; C1v.f = make_float2(C1, C1);
            F2 km0v; km0v.f = make_float2(km0, km0);
            F2 km1v; km1v.f = make_float2(km1, km1);
            char* dst = sE2 + q * 144 + k0 * 2;
            #pragma unroll
            for (int p = 0; p < 4; p++) {
                F2 x0 = bb2[p];
                ffma2(x0, A0v, w02[p]);
                ffma2(x0, C0v, w12[p]);
                F2 x1 = bb2[p];
                ffma2(x1, A1v, w02[p]);
                ffma2(x1, C1v, w12[p]);
                // exp(x) ~ deg-4 Taylor (|x| < 0.3)
                F2 t0 = P3;  ffma2(t0, x0, P4);
                F2 u0 = P2;  ffma2(u0, x0, t0);
                F2 v0 = ONE; ffma2(v0, x0, u0);
                F2 e0 = ONE; ffma2(e0, x0, v0);
                fmul2(e0, km0v);
                F2 t1 = P3;  ffma2(t1, x1, P4);
                F2 u1 = P2;  ffma2(u1, x1, t1);
                F2 v1 = ONE; ffma2(v1, x1, u1);
                F2 e1 = ONE; ffma2(e1, x1, v1);
                fmul2(e1, km1v);
                uint32_t rlo, rhi;
                CVT_BF2(rlo, e1.f.x, e0.f.x);          // head 2p,   (k0, k0+1)
                CVT_BF2(rhi, e1.f.y, e0.f.y);          // head 2p+1
                *(uint32_t*)(dst + (2 * p)     * 2304) = rlo;
                *(uint32_t*)(dst + (2 * p + 1) * 2304) = rhi;
            }
        }
        __syncthreads();

        // ---- Phase B: PV via tensor cores (+Z via ones column) ----
        #pragma unroll
        for (int s = 0; s < 4; s++) {
            uint32_t a0, a1, a2, a3;
            LDSM4(a0, a1, a2, a3, aBase + s * 32);
            #pragma unroll
            for (int t = 0; t < 2; t++) {
                uint32_t v0, v1, v2, v3;
                LDSM4T(v0, v1, v2, v3, bBase + s * 8448 + t * 32);
                MMA16816(d[2 * t],     a0, a1, a2, a3, v0, v1);
                MMA16816(d[2 * t + 1], a0, a1, a2, a3, v2, v3);
            }
            uint32_t o0, o1;
            LDSM2T(o0, o1, oBase + s * 8448);
            MMA16816(d[4], a0, a1, a2, a3, o0, o1);
        }
        __syncthreads();
    }

    // ---- Z: ones column (frag col 0 of n-tile 4), lanes with lane%4==0 ----
    if ((lane & 3) == 0) {
        sZ[wid * 16 + (lane >> 2)]     = d[4][0];
        sZ[wid * 16 + (lane >> 2) + 8] = d[4][2];
    }
    __syncthreads();

    // ---- epilogue: out = queries_it + (acc/Z) * query_mask ----
    #pragma unroll
    for (int rr = 0; rr < 2; rr++) {
        const int q = (lane >> 2) + rr * 8;
        const int qm = query_mask[b * LQ_ + qbase + q];
        const float invz = qm ? __frcp_rn(sZ[wid * 16 + q]) : 0.0f;
        const size_t rowbase = ((size_t)b * LQ_ + qbase + q) * 256 + wid * 32 + (lane & 3) * 2;
        #pragma unroll
        for (int t = 0; t < 4; t++) {
            float2 r = *(const float2*)(queries_it + rowbase + t * 8);
            r.x = fmaf(d[t][rr * 2 + 0], invz, r.x);
            r.y = fmaf(d[t][rr * 2 + 1], invz, r.y);
            *(float2*)(out + rowbase + t * 8) = r;
        }
    }
}

// =====================================================================
extern "C" void kernel_launch(void* const* d_in, const int* in_sizes, int n_in,
                              void* d_out, int out_size)
{
    (void)in_sizes; (void)n_in; (void)out_size;
    const float* queries_it  = (const float*)d_in[0];
    const float* queries_ctx = (const float*)d_in[1];
    const float* keys_it     = (const float*)d_in[2];
    const float* keys_ctx    = (const float*)d_in[3];
    const float* sigma       = (const float*)d_in[4];
    const float* noise       = (const float*)d_in[5];
    const float* Wq_it       = (const float*)d_in[6];
    const float* Wk_it       = (const float*)d_in[7];
    const float* Wq_ctx      = (const float*)d_in[8];
    const float* Wk_ctx      = (const float*)d_in[9];
    const float* Wv          = (const float*)d_in[10];
    const float* W_hdp       = (const float*)d_in[11];
    const float* b_hdp       = (const float*)d_in[12];
    const int*   key_mask    = (const int*)d_in[13];
    const int*   query_mask  = (const int*)d_in[14];
    float* out = (float*)d_out;

    cudaFuncSetAttribute(attn_kernel, cudaFuncAttributeMaxDynamicSharedMemorySize, ATTN_SMEM);

    proj_qk<<<dim3(64, B_, 2), 256>>>(queries_it, queries_ctx, keys_it, keys_ctx,
                                      Wq_it, Wq_ctx, Wk_it, Wk_ctx);
    proj_v<<<dim3(128, B_), 256>>>(keys_it, Wv);
    attn_kernel<<<dim3(LQ_ / 16, B_), 256, ATTN_SMEM>>>(
        noise, sigma, W_hdp, b_hdp, key_mask, query_mask, queries_it, out);
}

// round 13
// speedup vs baseline: 2.2231x; 1.0782x over previous
#include <cuda_runtime.h>
#include <cuda_bf16.h>
#include <cstdint>

#define B_  2
#define LQ_ 2048
#define LK_ 2048

// ---------------- scratch (__device__ globals: no allocation) ----------------
__device__ __nv_bfloat16  g_QFh[B_ * LQ_ * 64];       // [b][q][64]  bf16 (it | ctx)
__device__ __nv_bfloat16  g_KTh[B_ * 64 * LK_];       // [b][j][k]   bf16 (j: 0-31 it, 32-63 ctx)
__device__ __nv_bfloat16  g_VT [B_ * LK_ * 256];      // [b][k][256] bf16

// ---------------- packed f32x2 helpers ----------------
union F2 { unsigned long long u; float2 f; };

__device__ __forceinline__ void ffma2(F2& d, const F2& a, const F2& b) {
    asm("fma.rn.f32x2 %0, %1, %2, %0;" : "+l"(d.u) : "l"(a.u), "l"(b.u));
}
__device__ __forceinline__ void fmul2(F2& d, const F2& a) {
    asm("mul.rn.f32x2 %0, %0, %1;" : "+l"(d.u) : "l"(a.u));
}

// ---------------- tensor-core / async helpers ----------------
#define LDSM4(r0, r1, r2, r3, addr) \
    asm volatile("ldmatrix.sync.aligned.m8n8.x4.shared.b16 {%0,%1,%2,%3}, [%4];" \
        : "=r"(r0), "=r"(r1), "=r"(r2), "=r"(r3) : "r"(addr))
#define LDSM4T(r0, r1, r2, r3, addr) \
    asm volatile("ldmatrix.sync.aligned.m8n8.x4.trans.shared.b16 {%0,%1,%2,%3}, [%4];" \
        : "=r"(r0), "=r"(r1), "=r"(r2), "=r"(r3) : "r"(addr))
#define LDSM2T(r0, r1, addr) \
    asm volatile("ldmatrix.sync.aligned.m8n8.x2.trans.shared.b16 {%0,%1}, [%2];" \
        : "=r"(r0), "=r"(r1) : "r"(addr))
#define MMA16816(D, a0, a1, a2, a3, bb0, bb1) \
    asm volatile("mma.sync.aligned.m16n8k16.row.col.f32.bf16.bf16.f32 " \
        "{%0,%1,%2,%3}, {%4,%5,%6,%7}, {%8,%9}, {%0,%1,%2,%3};" \
        : "+f"(D[0]), "+f"(D[1]), "+f"(D[2]), "+f"(D[3]) \
        : "r"(a0), "r"(a1), "r"(a2), "r"(a3), "r"(bb0), "r"(bb1))
#define CVT_BF2(dst, hi, lo) \
    asm("cvt.rn.bf16x2.f32 %0, %1, %2;" : "=r"(dst) : "f"(hi), "f"(lo))
#define CP16(dst, src) \
    asm volatile("cp.async.cg.shared.global [%0], [%1], 16;" :: "r"(dst), "l"(src))
#define CP_COMMIT() asm volatile("cp.async.commit_group;")
#define CP_WAIT0()  asm volatile("cp.async.wait_group 0;")

// =====================================================================
// Q/K projection. grid (64, B, 2): z=0 -> Q, z=1 -> K. 512 threads.
// Warp-uniform column split (tid&63: 0-31 it, 32-63 ctx); 4 rows/thread.
// Same staging traffic as R10, 2x warps/SM for DRAM latency hiding.
// =====================================================================
__global__ __launch_bounds__(512) void proj_qk(
    const float* __restrict__ qit, const float* __restrict__ qctx,
    const float* __restrict__ kit, const float* __restrict__ kctx,
    const float* __restrict__ Wq_it, const float* __restrict__ Wq_ctx,
    const float* __restrict__ Wk_it, const float* __restrict__ Wk_ctx)
{
    __shared__ float sWit[256 * 32];   // 32KB
    __shared__ float sWct[128 * 32];   // 16KB
    const int mode = blockIdx.z;
    const float* in_it = mode ? kit : qit;
    const float* in_ct = mode ? kctx : qctx;
    const float* W_it  = mode ? Wk_it : Wq_it;
    const float* W_ct  = mode ? Wk_ctx : Wq_ctx;
    const int b = blockIdx.y;
    const int col = threadIdx.x & 63;
    const int isCtx = col >> 5;                 // warp-uniform
    const int j = col & 31;
    const int row0 = blockIdx.x * 32 + (threadIdx.x >> 6) * 4;

    for (int idx = threadIdx.x; idx < 256 * 32; idx += 512) sWit[idx] = W_it[idx];
    for (int idx = threadIdx.x; idx < 128 * 32; idx += 512) sWct[idx] = W_ct[idx];
    __syncthreads();

    const float* in = isCtx ? in_ct : in_it;
    const float* sW = isCtx ? sWct : sWit;
    const int nin4 = isCtx ? 32 : 64;           // float4 per input row

    const float4* p = (const float4*)(in + ((size_t)b * 2048 + row0) * (nin4 * 4));
    float a[4] = {0.f, 0.f, 0.f, 0.f};

    #pragma unroll 4
    for (int i4 = 0; i4 < nin4; i4++) {
        float4 v[4];
        #pragma unroll
        for (int r = 0; r < 4; r++) v[r] = p[r * nin4 + i4];
        #pragma unroll
        for (int ii = 0; ii < 4; ii++) {
            const float w = sW[(i4 * 4 + ii) * 32 + j];
            #pragma unroll
            for (int r = 0; r < 4; r++)
                a[r] = fmaf(((const float*)&v[r])[ii], w, a[r]);
        }
    }

    if (mode == 0) {
        #pragma unroll
        for (int r = 0; r < 4; r++)
            g_QFh[((size_t)b * 2048 + row0 + r) * 64 + col] = __float2bfloat16(a[r]);
    } else {
        __nv_bfloat16 pk[4];
        #pragma unroll
        for (int r = 0; r < 4; r++) pk[r] = __float2bfloat16(a[r]);
        *(uint2*)(g_KTh + ((size_t)b * 64 + col) * 2048 + row0) = *(const uint2*)pk;
    }
}

// =====================================================================
// V projection: 8 k-rows/block, grid (256, B) = 512 blocks (3.5/SM).
// =====================================================================
__global__ __launch_bounds__(256) void proj_v(
    const float* __restrict__ keys_it, const float* __restrict__ Wv)
{
    __shared__ float sKT[256][10];     // [i][r], pad 10 (8B-aligned float2 reads)
    const int b = blockIdx.y;
    const int kbase = blockIdx.x * 8;

    for (int idx = threadIdx.x; idx < 8 * 256; idx += 256) {
        const int r = idx >> 8, i = idx & 255;
        sKT[i][r] = keys_it[((size_t)b * 2048 + kbase + r) * 256 + i];
    }
    __syncthreads();

    const int hd = threadIdx.x;
    F2 acc[4];
    #pragma unroll
    for (int p = 0; p < 4; p++) acc[p].f = make_float2(0.0f, 0.0f);

    #pragma unroll 8
    for (int i = 0; i < 256; i++) {
        const float w = Wv[i * 256 + hd];
        F2 w2; w2.f = make_float2(w, w);
        #pragma unroll
        for (int p = 0; p < 4; p++) {
            F2 kp; kp.f = *reinterpret_cast<const float2*>(&sKT[i][2 * p]);
            ffma2(acc[p], kp, w2);
        }
    }

    __nv_bfloat16* o = g_VT + ((size_t)b * 2048 + kbase) * 256 + hd;
    #pragma unroll
    for (int p = 0; p < 4; p++) {
        o[(size_t)(2 * p) * 256]     = __float2bfloat16(acc[p].f.x);
        o[(size_t)(2 * p + 1) * 256] = __float2bfloat16(acc[p].f.y);
    }
}

// =====================================================================
// Attention: grid (LQ/16, B), 256 threads.
// Phase A: tensor-core QK (warp = key-octet) + fragment-local noise +
//          per-head poly-exp -> sE2[h][q][k] bf16.
// Phase B: tensor-core PV (warp = head) with ones-column Z.
// K,V double-buffered via cp.async (one commit group per tile, issued at
// tile top; wait_group 0 after phase B). 2 barriers/tile, zero extra regs.
// smem (bytes):
//   sQh bf16[16][72]  @0       (2304)
//   sK0 / sK1         @2304 / @11520   (9216 each)
//   sV0 / sV1         @20736 / @54528  (33792 each; cols 256..263 = ones)
//   sE2 bf16[8][16][72] @88320 (18432)
//   sZ  f32[8][16]    @106752  (512)      total 107264 -> 2 blocks/SM
// =====================================================================
#define ATTN_SMEM 107264

__global__ __launch_bounds__(256, 2) void attn_kernel(
    const float* __restrict__ noise, const float* __restrict__ sigma,
    const float* __restrict__ W_hdp, const float* __restrict__ b_hdp,
    const int* __restrict__ key_mask, const int* __restrict__ query_mask,
    const float* __restrict__ queries_it, float* __restrict__ out)
{
    extern __shared__ char dyn[];
    char*  sE2 = dyn + 88320;
    float* sZ  = (float*)(dyn + 106752);

    const int tid  = threadIdx.x;
    const int lane = tid & 31;
    const int wid  = tid >> 5;
    const int b = blockIdx.y;
    const int qbase = blockIdx.x * 16;
    const float SCALE = 0.17677669529663687f;   // 1/sqrt(32)

    const uint32_t sm_u  = (uint32_t)__cvta_generic_to_shared(dyn);
    const uint32_t sQh_u = sm_u;
    const uint32_t sK_u  = sm_u + 2304;
    const uint32_t sV_u  = sm_u + 20736;
    const uint32_t sE2_u = sm_u + 88320;

    const __nv_bfloat16* QFb = g_QFh + (size_t)b * LQ_ * 64;
    const __nv_bfloat16* KTb = g_KTh + (size_t)b * 64 * LK_;
    const __nv_bfloat16* Vb  = g_VT  + (size_t)b * LK_ * 256;
    const float* n0base = noise + (size_t)(b * 2 + 0) * LQ_ * LK_;
    const float* n1base = noise + (size_t)(b * 2 + 1) * LQ_ * LK_;

    // staging geometry
    const int kR = tid >> 3, kSeg = tid & 7;    // K: 2 chunks/thread (tid, tid+256)
    const int vR = tid >> 5, vSeg = tid & 31;   // V: 8 chunks/thread

    // ---- prologue: cp.async K(0), V(0) into buffer 0 ----
    #pragma unroll
    for (int p = 0; p < 2; p++) {
        const int idx = tid + 256 * p;
        const int r = idx >> 3, seg = idx & 7;
        CP16(sK_u + r * 144 + seg * 16, KTb + (size_t)r * LK_ + seg * 8);
    }
    #pragma unroll
    for (int p = 0; p < 8; p++) {
        const int idx = tid + 256 * p;
        const int kr = idx >> 5, seg = idx & 31;
        CP16(sV_u + kr * 528 + seg * 16, Vb + (size_t)kr * 256 + seg * 8);
    }
    CP_COMMIT();

    // Q tile (16 rows x 128B), sync stores
    if (tid < 128) {
        const int r = tid >> 3, seg = tid & 7;
        *(uint4*)(dyn + r * 144 + seg * 16) =
            *(const uint4*)(QFb + (size_t)(qbase + r) * 64 + seg * 8);
    }
    // ones-block cols 256..263 in BOTH V buffers (cp.async never touches them)
    for (int idx = tid; idx < 512; idx += 256) {
        const int r = idx >> 3, c = idx & 7;
        const __nv_bfloat16 v = __float2bfloat16(c == 0 ? 1.0f : 0.0f);
        *(__nv_bfloat16*)(dyn + 20736 + r * 528 + 512 + c * 2) = v;
        *(__nv_bfloat16*)(dyn + 54528 + r * 528 + 512 + c * 2) = v;
    }

    const float s0 = sigma[b * 2 + 0], s1 = sigma[b * 2 + 1];
    const float sig0sq = s0 * s0, sig1sq = s1 * s1;
    F2 w02[4], w12[4], bb2[4];
    #pragma unroll
    for (int p = 0; p < 4; p++) {
        w02[p].f = make_float2(W_hdp[2 * p] * SCALE,     W_hdp[2 * p + 1] * SCALE);
        w12[p].f = make_float2(W_hdp[8 + 2 * p] * SCALE, W_hdp[8 + 2 * p + 1] * SCALE);
        bb2[p].f = make_float2(b_hdp[2 * p] * SCALE,     b_hdp[2 * p + 1] * SCALE);
    }
    F2 P4; P4.f = make_float2(1.0f / 24.0f, 1.0f / 24.0f);
    F2 P3; P3.f = make_float2(1.0f / 6.0f,  1.0f / 6.0f);
    F2 P2; P2.f = make_float2(0.5f, 0.5f);
    F2 ONE; ONE.f = make_float2(1.0f, 1.0f);

    // phase A lane geometry (warp = key-octet)
    const int q_lo = lane >> 2;
    const int k0   = 8 * wid + 2 * (lane & 3);
    const uint32_t laneK = (uint32_t)(((lane & 7) + ((lane >> 3) & 1) * 8) * 144 + wid * 16);

    // phase B lane geometry (warp = head)
    const uint32_t aBase = sE2_u + wid * 2304
        + ((lane & 7) + ((lane >> 3) & 1) * 8) * 144
        + (lane >> 4) * 16;
    const int b_row  = (lane & 7) + (((lane >> 3) & 1) << 3);
    const int b_colb = (lane >> 4) * 16;
    const uint32_t laneV = (uint32_t)(b_row * 528 + b_colb);

    float d[5][4];
    #pragma unroll
    for (int t = 0; t < 5; t++)
        #pragma unroll
        for (int c = 0; c < 4; c++) d[t][c] = 0.0f;

    // Q A-fragments (persistent)
    CP_WAIT0();
    __syncthreads();
    uint32_t qa[4][4];
    {
        const uint32_t qaddr = sQh_u
            + ((lane & 7) + ((lane >> 3) & 1) * 8) * 144
            + (lane >> 4) * 16;
        #pragma unroll
        for (int c = 0; c < 4; c++)
            LDSM4(qa[c][0], qa[c][1], qa[c][2], qa[c][3], qaddr + c * 32);
    }

    for (int kt = 0; kt < LK_ / 64; kt++) {
        const int cur = kt & 1;
        const int tn = (kt + 1 < LK_ / 64) ? (kt + 1) : kt;
        const int kbaseN = tn * 64;

        // ---- prefetch K(t+1), V(t+1) into the other buffers (one group) ----
        {
            const uint32_t dK = sK_u + (1 - cur) * 9216;
            const uint32_t dV = sV_u + (1 - cur) * 33792;
            CP16(dK + kR * 144 + kSeg * 16,
                 KTb + (size_t)kR * LK_ + kbaseN + kSeg * 8);
            CP16(dK + (kR + 32) * 144 + kSeg * 16,
                 KTb + (size_t)(kR + 32) * LK_ + kbaseN + kSeg * 8);
            #pragma unroll
            for (int p = 0; p < 8; p++)
                CP16(dV + (vR + 8 * p) * 528 + vSeg * 16,
                     Vb + (size_t)(kbaseN + vR + 8 * p) * 256 + vSeg * 8);
            CP_COMMIT();
        }

        // ---- noise + mask (fragment-matched, sync) ----
        const int kg = kt * 64 + k0;
        const float2 n0a = *(const float2*)(n0base + (size_t)(qbase + q_lo)     * LK_ + kg);
        const float2 n0b = *(const float2*)(n0base + (size_t)(qbase + q_lo + 8) * LK_ + kg);
        const float2 n1a = *(const float2*)(n1base + (size_t)(qbase + q_lo)     * LK_ + kg);
        const float2 n1b = *(const float2*)(n1base + (size_t)(qbase + q_lo + 8) * LK_ + kg);
        const int2 kmv = *(const int2*)(key_mask + b * LK_ + kg);
        const float km0 = kmv.x ? 1.0f : 0.0f;
        const float km1 = kmv.y ? 1.0f : 0.0f;

        // ---- Phase A: QK via tensor cores (both streams) ----
        float dit[4] = {0.f, 0.f, 0.f, 0.f};
        float dct[4] = {0.f, 0.f, 0.f, 0.f};
        {
            const uint32_t kA = sK_u + cur * 9216 + laneK;
            uint32_t b0, b1;
            LDSM2T(b0, b1, kA);                        // it, j 0-15
            MMA16816(dit, qa[0][0], qa[0][1], qa[0][2], qa[0][3], b0, b1);
            LDSM2T(b0, b1, kA + 16 * 144);             // it, j 16-31
            MMA16816(dit, qa[1][0], qa[1][1], qa[1][2], qa[1][3], b0, b1);
            LDSM2T(b0, b1, kA + 32 * 144);             // ctx, j 32-47
            MMA16816(dct, qa[2][0], qa[2][1], qa[2][2], qa[2][3], b0, b1);
            LDSM2T(b0, b1, kA + 48 * 144);             // ctx, j 48-63
            MMA16816(dct, qa[3][0], qa[3][1], qa[3][2], qa[3][3], b0, b1);
        }

        // ---- noise add + per-head poly exp -> sE2[h][q][k] ----
        #pragma unroll
        for (int half = 0; half < 2; half++) {
            const int i0 = half * 2;
            const int q  = q_lo + half * 8;
            const float A0 = fmaf(sig0sq, half ? n0b.x : n0a.x, dit[i0]);
            const float A1 = fmaf(sig0sq, half ? n0b.y : n0a.y, dit[i0 + 1]);
            const float C0 = fmaf(sig1sq, half ? n1b.x : n1a.x, dct[i0]);
            const float C1 = fmaf(sig1sq, half ? n1b.y : n1a.y, dct[i0 + 1]);
            F2 A0v; A0v.f = make_float2(A0, A0);
            F2 A1v; A1v.f = make_float2(A1, A1);
            F2 C0v; C0v.f = make_float2(C0, C0);
            F2 C1v; C1v.f = make_float2(C1, C1);
            F2 km0v; km0v.f = make_float2(km0, km0);
            F2 km1v; km1v.f = make_float2(km1, km1);
            char* dst = sE2 + q * 144 + k0 * 2;
            #pragma unroll
            for (int p = 0; p < 4; p++) {
                F2 x0 = bb2[p];
                ffma2(x0, A0v, w02[p]);
                ffma2(x0, C0v, w12[p]);
                F2 x1 = bb2[p];
                ffma2(x1, A1v, w02[p]);
                ffma2(x1, C1v, w12[p]);
                F2 t0 = P3;  ffma2(t0, x0, P4);
                F2 u0 = P2;  ffma2(u0, x0, t0);
                F2 v0 = ONE; ffma2(v0, x0, u0);
                F2 e0 = ONE; ffma2(e0, x0, v0);
                fmul2(e0, km0v);
                F2 t1 = P3;  ffma2(t1, x1, P4);
                F2 u1 = P2;  ffma2(u1, x1, t1);
                F2 v1 = ONE; ffma2(v1, x1, u1);
                F2 e1 = ONE; ffma2(e1, x1, v1);
                fmul2(e1, km1v);
                uint32_t rlo, rhi;
                CVT_BF2(rlo, e1.f.x, e0.f.x);
                CVT_BF2(rhi, e1.f.y, e0.f.y);
                *(uint32_t*)(dst + (2 * p)     * 2304) = rlo;
                *(uint32_t*)(dst + (2 * p + 1) * 2304) = rhi;
            }
        }
        __syncthreads();

        // ---- Phase B: PV via tensor cores (+Z via ones column) ----
        {
            const uint32_t vB = sV_u + cur * 33792;
            const uint32_t bB = vB + laneV + wid * 64;
            const uint32_t oB = vB + b_row * 528 + 512;
            #pragma unroll
            for (int s = 0; s < 4; s++) {
                uint32_t a0, a1, a2, a3;
                LDSM4(a0, a1, a2, a3, aBase + s * 32);
                #pragma unroll
                for (int t = 0; t < 2; t++) {
                    uint32_t v0, v1, v2, v3;
                    LDSM4T(v0, v1, v2, v3, bB + s * 8448 + t * 32);
                    MMA16816(d[2 * t],     a0, a1, a2, a3, v0, v1);
                    MMA16816(d[2 * t + 1], a0, a1, a2, a3, v2, v3);
                }
                uint32_t o0, o1;
                LDSM2T(o0, o1, oB + s * 8448);
                MMA16816(d[4], a0, a1, a2, a3, o0, o1);
            }
        }

        CP_WAIT0();        // K(t+1), V(t+1) landed
        __syncthreads();   // sE consumed by all; buffers swappable
    }

    // ---- Z: ones column (frag col 0 of n-tile 4), lanes with lane%4==0 ----
    if ((lane & 3) == 0) {
        sZ[wid * 16 + (lane >> 2)]     = d[4][0];
        sZ[wid * 16 + (lane >> 2) + 8] = d[4][2];
    }
    __syncthreads();

    // ---- epilogue: out = queries_it + (acc/Z) * query_mask ----
    #pragma unroll
    for (int rr = 0; rr < 2; rr++) {
        const int q = (lane >> 2) + rr * 8;
        const int qm = query_mask[b * LQ_ + qbase + q];
        const float invz = qm ? __frcp_rn(sZ[wid * 16 + q]) : 0.0f;
        const size_t rowbase = ((size_t)b * LQ_ + qbase + q) * 256 + wid * 32 + (lane & 3) * 2;
        #pragma unroll
        for (int t = 0; t < 4; t++) {
            float2 r = *(const float2*)(queries_it + rowbase + t * 8);
            r.x = fmaf(d[t][rr * 2 + 0], invz, r.x);
            r.y = fmaf(d[t][rr * 2 + 1], invz, r.y);
            *(float2*)(out + rowbase + t * 8) = r;
        }
    }
}

// =====================================================================
extern "C" void kernel_launch(void* const* d_in, const int* in_sizes, int n_in,
                              void* d_out, int out_size)
{
    (void)in_sizes; (void)n_in; (void)out_size;
    const float* queries_it  = (const float*)d_in[0];
    const float* queries_ctx = (const float*)d_in[1];
    const float* keys_it     = (const float*)d_in[2];
    const float* keys_ctx    = (const float*)d_in[3];
    const float* sigma       = (const float*)d_in[4];
    const float* noise       = (const float*)d_in[5];
    const float* Wq_it       = (const float*)d_in[6];
    const float* Wk_it       = (const float*)d_in[7];
    const float* Wq_ctx      = (const float*)d_in[8];
    const float* Wk_ctx      = (const float*)d_in[9];
    const float* Wv          = (const float*)d_in[10];
    const float* W_hdp       = (const float*)d_in[11];
    const float* b_hdp       = (const float*)d_in[12];
    const int*   key_mask    = (const int*)d_in[13];
    const int*   query_mask  = (const int*)d_in[14];
    float* out = (float*)d_out;

    cudaFuncSetAttribute(attn_kernel, cudaFuncAttributeMaxDynamicSharedMemorySize, ATTN_SMEM);

    proj_qk<<<dim3(64, B_, 2), 512>>>(queries_it, queries_ctx, keys_it, keys_ctx,
                                      Wq_it, Wq_ctx, Wk_it, Wk_ctx);
    proj_v<<<dim3(256, B_), 256>>>(keys_it, Wv);
    attn_kernel<<<dim3(LQ_ / 16, B_), 256, ATTN_SMEM>>>(
        noise, sigma, W_hdp, b_hdp, key_mask, query_mask, queries_it, out);
}

// round 14
// speedup vs baseline: 2.5250x; 1.1358x over previous
#include <cuda_runtime.h>
#include <cuda_bf16.h>
#include <cstdint>

#define B_  2
#define LQ_ 2048
#define LK_ 2048

// ---------------- scratch (__device__ globals: no allocation) ----------------
__device__ __nv_bfloat16  g_QFh[B_ * LQ_ * 64];       // [b][q][64]  bf16 (it | ctx)
__device__ __nv_bfloat16  g_KTh[B_ * 64 * LK_];       // [b][j][k]   bf16 (j: 0-31 it, 32-63 ctx)
__device__ __nv_bfloat16  g_VT [B_ * LK_ * 256];      // [b][k][256] bf16

// ---------------- packed f32x2 helpers ----------------
union F2 { unsigned long long u; float2 f; };

__device__ __forceinline__ void ffma2(F2& d, const F2& a, const F2& b) {
    asm("fma.rn.f32x2 %0, %1, %2, %0;" : "+l"(d.u) : "l"(a.u), "l"(b.u));
}
__device__ __forceinline__ void fmul2(F2& d, const F2& a) {
    asm("mul.rn.f32x2 %0, %0, %1;" : "+l"(d.u) : "l"(a.u));
}

// ---------------- tensor-core / async helpers ----------------
#define LDSM4(r0, r1, r2, r3, addr) \
    asm volatile("ldmatrix.sync.aligned.m8n8.x4.shared.b16 {%0,%1,%2,%3}, [%4];" \
        : "=r"(r0), "=r"(r1), "=r"(r2), "=r"(r3) : "r"(addr))
#define LDSM4T(r0, r1, r2, r3, addr) \
    asm volatile("ldmatrix.sync.aligned.m8n8.x4.trans.shared.b16 {%0,%1,%2,%3}, [%4];" \
        : "=r"(r0), "=r"(r1), "=r"(r2), "=r"(r3) : "r"(addr))
#define LDSM2T(r0, r1, addr) \
    asm volatile("ldmatrix.sync.aligned.m8n8.x2.trans.shared.b16 {%0,%1}, [%2];" \
        : "=r"(r0), "=r"(r1) : "r"(addr))
#define MMA16816(D, a0, a1, a2, a3, bb0, bb1) \
    asm volatile("mma.sync.aligned.m16n8k16.row.col.f32.bf16.bf16.f32 " \
        "{%0,%1,%2,%3}, {%4,%5,%6,%7}, {%8,%9}, {%0,%1,%2,%3};" \
        : "+f"(D[0]), "+f"(D[1]), "+f"(D[2]), "+f"(D[3]) \
        : "r"(a0), "r"(a1), "r"(a2), "r"(a3), "r"(bb0), "r"(bb1))
#define CVT_BF2(dst, hi, lo) \
    asm("cvt.rn.bf16x2.f32 %0, %1, %2;" : "=r"(dst) : "f"(hi), "f"(lo))
#define CP16(dst, src) \
    asm volatile("cp.async.cg.shared.global [%0], [%1], 16;" :: "r"(dst), "l"(src))
#define CP_COMMIT() asm volatile("cp.async.commit_group;")
#define CP_WAIT0()  asm volatile("cp.async.wait_group 0;")

// =====================================================================
// Q/K projection as tiled register-blocked GEMM.
// grid (32, B, 2): z=0 -> Q, z=1 -> K. 256 threads, 64 rows x 64 cols/block.
// Warps 0-3: it-GEMM (cols 0-31, k=256). Warps 4-7: ctx-GEMM (cols 32-63, k=128).
// k-tiles of 32; A staged transposed (As[kk][row]) for LDS.128; 4x4 reg tile.
// =====================================================================
__global__ __launch_bounds__(256) void proj_qk(
    const float* __restrict__ qit, const float* __restrict__ qctx,
    const float* __restrict__ kit, const float* __restrict__ kctx,
    const float* __restrict__ Wq_it, const float* __restrict__ Wq_ctx,
    const float* __restrict__ Wk_it, const float* __restrict__ Wk_ctx)
{
    __shared__ float Asi[32][68];   // it  A tile, transposed  8.7KB
    __shared__ float Wsi[32][36];   // it  W tile              4.6KB
    __shared__ float Asc[32][68];   // ctx A tile              8.7KB
    __shared__ float Wsc[32][36];   // ctx W tile              4.6KB

    const int mode = blockIdx.z;
    const float* in_it = mode ? kit : qit;
    const float* in_ct = mode ? kctx : qctx;
    const float* W_it  = mode ? Wk_it : Wq_it;
    const float* W_ct  = mode ? Wk_ctx : Wq_ctx;
    const int b = blockIdx.y;
    const int rowbase = blockIdx.x * 64;
    const int tid = threadIdx.x;

    const int isCtx = tid >> 7;                 // warp-uniform (warps 4-7)
    const int tl = tid & 127;
    const int r0 = (tl >> 3) * 4;               // local rows r0..r0+3
    const int c0 = (tl & 7) * 4;                // local cols (within half)

    const float* Ain = in_it + ((size_t)b * 2048 + rowbase) * 256;
    const float* Cin = in_ct + ((size_t)b * 2048 + rowbase) * 128;

    // staging ids
    const int sRow = tid >> 3, sF4 = tid & 7;   // A: row, float4-idx (2 reps)
    const int wKK = tid >> 3, wC4 = tid & 7;    // W: kk, col-quad

    float acc[4][4];
    #pragma unroll
    for (int r = 0; r < 4; r++)
        #pragma unroll
        for (int c = 0; c < 4; c++) acc[r][c] = 0.0f;

    #pragma unroll 1
    for (int t = 0; t < 8; t++) {
        // ---- stage it tile (A transposed + W) ----
        {
            float4 v = *(const float4*)(Ain + (size_t)sRow * 256 + t * 32 + sF4 * 4);
            Asi[sF4 * 4 + 0][sRow] = v.x;
            Asi[sF4 * 4 + 1][sRow] = v.y;
            Asi[sF4 * 4 + 2][sRow] = v.z;
            Asi[sF4 * 4 + 3][sRow] = v.w;
            float4 v2 = *(const float4*)(Ain + (size_t)(sRow + 32) * 256 + t * 32 + sF4 * 4);
            Asi[sF4 * 4 + 0][sRow + 32] = v2.x;
            Asi[sF4 * 4 + 1][sRow + 32] = v2.y;
            Asi[sF4 * 4 + 2][sRow + 32] = v2.z;
            Asi[sF4 * 4 + 3][sRow + 32] = v2.w;
            *(float4*)&Wsi[wKK][wC4 * 4] =
                *(const float4*)(W_it + (size_t)(t * 32 + wKK) * 32 + wC4 * 4);
        }
        // ---- stage ctx tile (only t < 4) ----
        if (t < 4) {
            float4 v = *(const float4*)(Cin + (size_t)sRow * 128 + t * 32 + sF4 * 4);
            Asc[sF4 * 4 + 0][sRow] = v.x;
            Asc[sF4 * 4 + 1][sRow] = v.y;
            Asc[sF4 * 4 + 2][sRow] = v.z;
            Asc[sF4 * 4 + 3][sRow] = v.w;
            float4 v2 = *(const float4*)(Cin + (size_t)(sRow + 32) * 128 + t * 32 + sF4 * 4);
            Asc[sF4 * 4 + 0][sRow + 32] = v2.x;
            Asc[sF4 * 4 + 1][sRow + 32] = v2.y;
            Asc[sF4 * 4 + 2][sRow + 32] = v2.z;
            Asc[sF4 * 4 + 3][sRow + 32] = v2.w;
            *(float4*)&Wsc[wKK][wC4 * 4] =
                *(const float4*)(W_ct + (size_t)(t * 32 + wKK) * 32 + wC4 * 4);
        }
        __syncthreads();

        // ---- compute ----
        if (!isCtx) {
            #pragma unroll 8
            for (int kk = 0; kk < 32; kk++) {
                const float4 a4 = *(const float4*)&Asi[kk][r0];
                const float4 w4 = *(const float4*)&Wsi[kk][c0];
                const float av[4] = {a4.x, a4.y, a4.z, a4.w};
                const float wv[4] = {w4.x, w4.y, w4.z, w4.w};
                #pragma unroll
                for (int r = 0; r < 4; r++)
                    #pragma unroll
                    for (int c = 0; c < 4; c++)
                        acc[r][c] = fmaf(av[r], wv[c], acc[r][c]);
            }
        } else if (t < 4) {
            #pragma unroll 8
            for (int kk = 0; kk < 32; kk++) {
                const float4 a4 = *(const float4*)&Asc[kk][r0];
                const float4 w4 = *(const float4*)&Wsc[kk][c0];
                const float av[4] = {a4.x, a4.y, a4.z, a4.w};
                const float wv[4] = {w4.x, w4.y, w4.z, w4.w};
                #pragma unroll
                for (int r = 0; r < 4; r++)
                    #pragma unroll
                    for (int c = 0; c < 4; c++)
                        acc[r][c] = fmaf(av[r], wv[c], acc[r][c]);
            }
        }
        __syncthreads();
    }

    const int colg = isCtx ? (32 + c0) : c0;    // global output col base
    if (mode == 0) {
        // Q: g_QFh[b][row][col], 4 cols per row -> uint2
        #pragma unroll
        for (int r = 0; r < 4; r++) {
            __nv_bfloat16 pk[4];
            #pragma unroll
            for (int c = 0; c < 4; c++) pk[c] = __float2bfloat16(acc[r][c]);
            *(uint2*)(g_QFh + ((size_t)b * 2048 + rowbase + r0 + r) * 64 + colg) =
                *(const uint2*)pk;
        }
    } else {
        // K: g_KTh[b][col][k=row], 4 rows per col -> uint2
        #pragma unroll
        for (int c = 0; c < 4; c++) {
            __nv_bfloat16 pk[4];
            #pragma unroll
            for (int r = 0; r < 4; r++) pk[r] = __float2bfloat16(acc[r][c]);
            *(uint2*)(g_KTh + ((size_t)b * 64 + colg + c) * 2048 + rowbase + r0) =
                *(const uint2*)pk;
        }
    }
}

// =====================================================================
// V projection: 8 k-rows/block, grid (256, B) = 512 blocks.
// =====================================================================
__global__ __launch_bounds__(256) void proj_v(
    const float* __restrict__ keys_it, const float* __restrict__ Wv)
{
    __shared__ float sKT[256][10];
    const int b = blockIdx.y;
    const int kbase = blockIdx.x * 8;

    for (int idx = threadIdx.x; idx < 8 * 256; idx += 256) {
        const int r = idx >> 8, i = idx & 255;
        sKT[i][r] = keys_it[((size_t)b * 2048 + kbase + r) * 256 + i];
    }
    __syncthreads();

    const int hd = threadIdx.x;
    F2 acc[4];
    #pragma unroll
    for (int p = 0; p < 4; p++) acc[p].f = make_float2(0.0f, 0.0f);

    #pragma unroll 8
    for (int i = 0; i < 256; i++) {
        const float w = Wv[i * 256 + hd];
        F2 w2; w2.f = make_float2(w, w);
        #pragma unroll
        for (int p = 0; p < 4; p++) {
            F2 kp; kp.f = *reinterpret_cast<const float2*>(&sKT[i][2 * p]);
            ffma2(acc[p], kp, w2);
        }
    }

    __nv_bfloat16* o = g_VT + ((size_t)b * 2048 + kbase) * 256 + hd;
    #pragma unroll
    for (int p = 0; p < 4; p++) {
        o[(size_t)(2 * p) * 256]     = __float2bfloat16(acc[p].f.x);
        o[(size_t)(2 * p + 1) * 256] = __float2bfloat16(acc[p].f.y);
    }
}

// =====================================================================
// Attention (R12-proven): grid (LQ/16, B), 256 threads.
// Noise loads hoisted to tile top with __ldcs (streaming, evict-first).
// =====================================================================
#define ATTN_SMEM 107264

__global__ __launch_bounds__(256, 2) void attn_kernel(
    const float* __restrict__ noise, const float* __restrict__ sigma,
    const float* __restrict__ W_hdp, const float* __restrict__ b_hdp,
    const int* __restrict__ key_mask, const int* __restrict__ query_mask,
    const float* __restrict__ queries_it, float* __restrict__ out)
{
    extern __shared__ char dyn[];
    char*  sE2 = dyn + 88320;
    float* sZ  = (float*)(dyn + 106752);

    const int tid  = threadIdx.x;
    const int lane = tid & 31;
    const int wid  = tid >> 5;
    const int b = blockIdx.y;
    const int qbase = blockIdx.x * 16;
    const float SCALE = 0.17677669529663687f;   // 1/sqrt(32)

    const uint32_t sm_u  = (uint32_t)__cvta_generic_to_shared(dyn);
    const uint32_t sQh_u = sm_u;
    const uint32_t sK_u  = sm_u + 2304;
    const uint32_t sV_u  = sm_u + 20736;
    const uint32_t sE2_u = sm_u + 88320;

    const __nv_bfloat16* QFb = g_QFh + (size_t)b * LQ_ * 64;
    const __nv_bfloat16* KTb = g_KTh + (size_t)b * 64 * LK_;
    const __nv_bfloat16* Vb  = g_VT  + (size_t)b * LK_ * 256;
    const float* n0base = noise + (size_t)(b * 2 + 0) * LQ_ * LK_;
    const float* n1base = noise + (size_t)(b * 2 + 1) * LQ_ * LK_;

    const int kR = tid >> 3, kSeg = tid & 7;
    const int vR = tid >> 5, vSeg = tid & 31;

    // ---- prologue: cp.async K(0), V(0) into buffer 0 ----
    #pragma unroll
    for (int p = 0; p < 2; p++) {
        const int idx = tid + 256 * p;
        const int r = idx >> 3, seg = idx & 7;
        CP16(sK_u + r * 144 + seg * 16, KTb + (size_t)r * LK_ + seg * 8);
    }
    #pragma unroll
    for (int p = 0; p < 8; p++) {
        const int idx = tid + 256 * p;
        const int kr = idx >> 5, seg = idx & 31;
        CP16(sV_u + kr * 528 + seg * 16, Vb + (size_t)kr * 256 + seg * 8);
    }
    CP_COMMIT();

    if (tid < 128) {
        const int r = tid >> 3, seg = tid & 7;
        *(uint4*)(dyn + r * 144 + seg * 16) =
            *(const uint4*)(QFb + (size_t)(qbase + r) * 64 + seg * 8);
    }
    for (int idx = tid; idx < 512; idx += 256) {
        const int r = idx >> 3, c = idx & 7;
        const __nv_bfloat16 v = __float2bfloat16(c == 0 ? 1.0f : 0.0f);
        *(__nv_bfloat16*)(dyn + 20736 + r * 528 + 512 + c * 2) = v;
        *(__nv_bfloat16*)(dyn + 54528 + r * 528 + 512 + c * 2) = v;
    }

    const float s0 = sigma[b * 2 + 0], s1 = sigma[b * 2 + 1];
    const float sig0sq = s0 * s0, sig1sq = s1 * s1;
    F2 w02[4], w12[4], bb2[4];
    #pragma unroll
    for (int p = 0; p < 4; p++) {
        w02[p].f = make_float2(W_hdp[2 * p] * SCALE,     W_hdp[2 * p + 1] * SCALE);
        w12[p].f = make_float2(W_hdp[8 + 2 * p] * SCALE, W_hdp[8 + 2 * p + 1] * SCALE);
        bb2[p].f = make_float2(b_hdp[2 * p] * SCALE,     b_hdp[2 * p + 1] * SCALE);
    }
    F2 P4; P4.f = make_float2(1.0f / 24.0f, 1.0f / 24.0f);
    F2 P3; P3.f = make_float2(1.0f / 6.0f,  1.0f / 6.0f);
    F2 P2; P2.f = make_float2(0.5f, 0.5f);
    F2 ONE; ONE.f = make_float2(1.0f, 1.0f);

    const int q_lo = lane >> 2;
    const int k0   = 8 * wid + 2 * (lane & 3);
    const uint32_t laneK = (uint32_t)(((lane & 7) + ((lane >> 3) & 1) * 8) * 144 + wid * 16);

    const uint32_t aBase = sE2_u + wid * 2304
        + ((lane & 7) + ((lane >> 3) & 1) * 8) * 144
        + (lane >> 4) * 16;
    const int b_row  = (lane & 7) + (((lane >> 3) & 1) << 3);
    const int b_colb = (lane >> 4) * 16;
    const uint32_t laneV = (uint32_t)(b_row * 528 + b_colb);

    float d[5][4];
    #pragma unroll
    for (int t = 0; t < 5; t++)
        #pragma unroll
        for (int c = 0; c < 4; c++) d[t][c] = 0.0f;

    CP_WAIT0();
    __syncthreads();
    uint32_t qa[4][4];
    {
        const uint32_t qaddr = sQh_u
            + ((lane & 7) + ((lane >> 3) & 1) * 8) * 144
            + (lane >> 4) * 16;
        #pragma unroll
        for (int c = 0; c < 4; c++)
            LDSM4(qa[c][0], qa[c][1], qa[c][2], qa[c][3], qaddr + c * 32);
    }

    for (int kt = 0; kt < LK_ / 64; kt++) {
        const int cur = kt & 1;
        const int tn = (kt + 1 < LK_ / 64) ? (kt + 1) : kt;
        const int kbaseN = tn * 64;

        // ---- noise + mask first (streaming loads; longest cover window) ----
        const int kg = kt * 64 + k0;
        const float2 n0a = __ldcs((const float2*)(n0base + (size_t)(qbase + q_lo)     * LK_ + kg));
        const float2 n0b = __ldcs((const float2*)(n0base + (size_t)(qbase + q_lo + 8) * LK_ + kg));
        const float2 n1a = __ldcs((const float2*)(n1base + (size_t)(qbase + q_lo)     * LK_ + kg));
        const float2 n1b = __ldcs((const float2*)(n1base + (size_t)(qbase + q_lo + 8) * LK_ + kg));
        const int2 kmv = *(const int2*)(key_mask + b * LK_ + kg);
        const float km0 = kmv.x ? 1.0f : 0.0f;
        const float km1 = kmv.y ? 1.0f : 0.0f;

        // ---- prefetch K(t+1), V(t+1) into the other buffers ----
        {
            const uint32_t dK = sK_u + (1 - cur) * 9216;
            const uint32_t dV = sV_u + (1 - cur) * 33792;
            CP16(dK + kR * 144 + kSeg * 16,
                 KTb + (size_t)kR * LK_ + kbaseN + kSeg * 8);
            CP16(dK + (kR + 32) * 144 + kSeg * 16,
                 KTb + (size_t)(kR + 32) * LK_ + kbaseN + kSeg * 8);
            #pragma unroll
            for (int p = 0; p < 8; p++)
                CP16(dV + (vR + 8 * p) * 528 + vSeg * 16,
                     Vb + (size_t)(kbaseN + vR + 8 * p) * 256 + vSeg * 8);
            CP_COMMIT();
        }

        // ---- Phase A: QK via tensor cores (both streams) ----
        float dit[4] = {0.f, 0.f, 0.f, 0.f};
        float dct[4] = {0.f, 0.f, 0.f, 0.f};
        {
            const uint32_t kA = sK_u + cur * 9216 + laneK;
            uint32_t b0, b1;
            LDSM2T(b0, b1, kA);
            MMA16816(dit, qa[0][0], qa[0][1], qa[0][2], qa[0][3], b0, b1);
            LDSM2T(b0, b1, kA + 16 * 144);
            MMA16816(dit, qa[1][0], qa[1][1], qa[1][2], qa[1][3], b0, b1);
            LDSM2T(b0, b1, kA + 32 * 144);
            MMA16816(dct, qa[2][0], qa[2][1], qa[2][2], qa[2][3], b0, b1);
            LDSM2T(b0, b1, kA + 48 * 144);
            MMA16816(dct, qa[3][0], qa[3][1], qa[3][2], qa[3][3], b0, b1);
        }

        // ---- noise add + per-head poly exp -> sE2[h][q][k] ----
        #pragma unroll
        for (int half = 0; half < 2; half++) {
            const int i0 = half * 2;
            const int q  = q_lo + half * 8;
            const float A0 = fmaf(sig0sq, half ? n0b.x : n0a.x, dit[i0]);
            const float A1 = fmaf(sig0sq, half ? n0b.y : n0a.y, dit[i0 + 1]);
            const float C0 = fmaf(sig1sq, half ? n1b.x : n1a.x, dct[i0]);
            const float C1 = fmaf(sig1sq, half ? n1b.y : n1a.y, dct[i0 + 1]);
            F2 A0v; A0v.f = make_float2(A0, A0);
            F2 A1v; A1v.f = make_float2(A1, A1);
            F2 C0v; C0v.f = make_float2(C0, C0);
            F2 C1v; C1v.f = make_float2(C1, C1);
            F2 km0v; km0v.f = make_float2(km0, km0);
            F2 km1v; km1v.f = make_float2(km1, km1);
            char* dst = sE2 + q * 144 + k0 * 2;
            #pragma unroll
            for (int p = 0; p < 4; p++) {
                F2 x0 = bb2[p];
                ffma2(x0, A0v, w02[p]);
                ffma2(x0, C0v, w12[p]);
                F2 x1 = bb2[p];
                ffma2(x1, A1v, w02[p]);
                ffma2(x1, C1v, w12[p]);
                F2 t0 = P3;  ffma2(t0, x0, P4);
                F2 u0 = P2;  ffma2(u0, x0, t0);
                F2 v0 = ONE; ffma2(v0, x0, u0);
                F2 e0 = ONE; ffma2(e0, x0, v0);
                fmul2(e0, km0v);
                F2 t1 = P3;  ffma2(t1, x1, P4);
                F2 u1 = P2;  ffma2(u1, x1, t1);
                F2 v1 = ONE; ffma2(v1, x1, u1);
                F2 e1 = ONE; ffma2(e1, x1, v1);
                fmul2(e1, km1v);
                uint32_t rlo, rhi;
                CVT_BF2(rlo, e1.f.x, e0.f.x);
                CVT_BF2(rhi, e1.f.y, e0.f.y);
                *(uint32_t*)(dst + (2 * p)     * 2304) = rlo;
                *(uint32_t*)(dst + (2 * p + 1) * 2304) = rhi;
            }
        }
        __syncthreads();

        // ---- Phase B: PV via tensor cores (+Z via ones column) ----
        {
            const uint32_t vB = sV_u + cur * 33792;
            const uint32_t bB = vB + laneV + wid * 64;
            const uint32_t oB = vB + b_row * 528 + 512;
            #pragma unroll
            for (int s = 0; s < 4; s++) {
                uint32_t a0, a1, a2, a3;
                LDSM4(a0, a1, a2, a3, aBase + s * 32);
                #pragma unroll
                for (int t = 0; t < 2; t++) {
                    uint32_t v0, v1, v2, v3;
                    LDSM4T(v0, v1, v2, v3, bB + s * 8448 + t * 32);
                    MMA16816(d[2 * t],     a0, a1, a2, a3, v0, v1);
                    MMA16816(d[2 * t + 1], a0, a1, a2, a3, v2, v3);
                }
                uint32_t o0, o1;
                LDSM2T(o0, o1, oB + s * 8448);
                MMA16816(d[4], a0, a1, a2, a3, o0, o1);
            }
        }

        CP_WAIT0();
        __syncthreads();
    }

    if ((lane & 3) == 0) {
        sZ[wid * 16 + (lane >> 2)]     = d[4][0];
        sZ[wid * 16 + (lane >> 2) + 8] = d[4][2];
    }
    __syncthreads();

    #pragma unroll
    for (int rr = 0; rr < 2; rr++) {
        const int q = (lane >> 2) + rr * 8;
        const int qm = query_mask[b * LQ_ + qbase + q];
        const float invz = qm ? __frcp_rn(sZ[wid * 16 + q]) : 0.0f;
        const size_t rowbase = ((size_t)b * LQ_ + qbase + q) * 256 + wid * 32 + (lane & 3) * 2;
        #pragma unroll
        for (int t = 0; t < 4; t++) {
            float2 r = *(const float2*)(queries_it + rowbase + t * 8);
            r.x = fmaf(d[t][rr * 2 + 0], invz, r.x);
            r.y = fmaf(d[t][rr * 2 + 1], invz, r.y);
            *(float2*)(out + rowbase + t * 8) = r;
        }
    }
}

// =====================================================================
extern "C" void kernel_launch(void* const* d_in, const int* in_sizes, int n_in,
                              void* d_out, int out_size)
{
    (void)in_sizes; (void)n_in; (void)out_size;
    const float* queries_it  = (const float*)d_in[0];
    const float* queries_ctx = (const float*)d_in[1];
    const float* keys_it     = (const float*)d_in[2];
    const float* keys_ctx    = (const float*)d_in[3];
    const float* sigma       = (const float*)d_in[4];
    const float* noise       = (const float*)d_in[5];
    const float* Wq_it       = (const float*)d_in[6];
    const float* Wk_it       = (const float*)d_in[7];
    const float* Wq_ctx      = (const float*)d_in[8];
    const float* Wk_ctx      = (const float*)d_in[9];
    const float* Wv          = (const float*)d_in[10];
    const float* W_hdp       = (const float*)d_in[11];
    const float* b_hdp       = (const float*)d_in[12];
    const int*   key_mask    = (const int*)d_in[13];
    const int*   query_mask  = (const int*)d_in[14];
    float* out = (float*)d_out;

    cudaFuncSetAttribute(attn_kernel, cudaFuncAttributeMaxDynamicSharedMemorySize, ATTN_SMEM);

    proj_qk<<<dim3(32, B_, 2), 256>>>(queries_it, queries_ctx, keys_it, keys_ctx,
                                      Wq_it, Wq_ctx, Wk_it, Wk_ctx);
    proj_v<<<dim3(256, B_), 256>>>(keys_it, Wv);
    attn_kernel<<<dim3(LQ_ / 16, B_), 256, ATTN_SMEM>>>(
        noise, sigma, W_hdp, b_hdp, key_mask, query_mask, queries_it, out);
}